// round 3
// baseline (speedup 1.0000x reference)
#include <cuda_runtime.h>
#include <cstdint>
#include <math.h>

// ---------------------------------------------------------------------------
// Swin-style block:
//  LN1 -> shift(-4,-4) -> 8x8 window partition (q from D=0, kv from D=1)
//  q/kv projections -> windowed MHA (8 heads, d=32, rel-pos bias + mask)
//  -> proj + residual(q_in) -> window reverse -> shift(+4,+4) -> +x[:,0]
//  -> LN2 -> MLP (C->4C gelu -> C) -> residual
// All fp32. Staged kernels with static __device__ scratch.
// ---------------------------------------------------------------------------

#define MROWS 131072          // B*nwin*N = 2*1024*64 tokens
#define HID   1024

__device__ float g_qin [(size_t)MROWS * 256];
__device__ float g_kvin[(size_t)MROWS * 256];
__device__ float g_q   [(size_t)MROWS * 256];
__device__ float g_kv  [(size_t)MROWS * 512];
__device__ float g_ao  [(size_t)MROWS * 256];
__device__ float g_po  [(size_t)MROWS * 256];
__device__ float g_x1  [(size_t)MROWS * 256];
__device__ float g_x1n [(size_t)MROWS * 256];
__device__ float g_h   [(size_t)MROWS * HID];

// ---------------------------------------------------------------------------
// K1: LayerNorm + shift + window partition. One warp per output row.
// warp id = d*131072 + (wi*64 + n);   d=0 -> q_in, d=1 -> kv_in
// ---------------------------------------------------------------------------
__global__ void ln_window_kernel(const float* __restrict__ x,
                                 const float* __restrict__ g,
                                 const float* __restrict__ b,
                                 float* __restrict__ qin,
                                 float* __restrict__ kvin)
{
    int warp = (blockIdx.x * blockDim.x + threadIdx.x) >> 5;
    int lane = threadIdx.x & 31;
    int d  = warp >> 17;
    int r  = warp & 131071;
    int wi = r >> 6, n = r & 63;
    int bb = wi >> 10, wl = wi & 1023;
    int wh = wl >> 5,  wc = wl & 31;
    int i  = n >> 3,   j  = n & 7;
    int hs = (wh * 8 + i + 4) & 255;   // roll(-4)
    int ws = (wc * 8 + j + 4) & 255;
    const float* src = x + ((((size_t)(bb * 2 + d) * 256 + hs) * 256 + ws) << 8);

    float v[8]; float s = 0.f;
#pragma unroll
    for (int k = 0; k < 8; k++) { v[k] = src[lane + k * 32]; s += v[k]; }
#pragma unroll
    for (int o = 16; o; o >>= 1) s += __shfl_xor_sync(0xffffffffu, s, o);
    float mean = s * (1.f / 256.f);
    float vs = 0.f;
#pragma unroll
    for (int k = 0; k < 8; k++) { float t = v[k] - mean; vs += t * t; }
#pragma unroll
    for (int o = 16; o; o >>= 1) vs += __shfl_xor_sync(0xffffffffu, vs, o);
    float rstd = rsqrtf(vs * (1.f / 256.f) + 1e-5f);

    float* dst = (d == 0 ? qin : kvin) + ((size_t)r << 8);
#pragma unroll
    for (int k = 0; k < 8; k++) {
        int c = lane + k * 32;
        dst[c] = (v[k] - mean) * rstd * g[c] + b[c];
    }
}

// ---------------------------------------------------------------------------
// Plain row LayerNorm (for LN2 on x1). One warp per row, 131072 rows.
// ---------------------------------------------------------------------------
__global__ void ln_rows_kernel(const float* __restrict__ in,
                               const float* __restrict__ g,
                               const float* __restrict__ b,
                               float* __restrict__ out)
{
    int warp = (blockIdx.x * blockDim.x + threadIdx.x) >> 5;
    int lane = threadIdx.x & 31;
    const float* src = in + ((size_t)warp << 8);
    float v[8]; float s = 0.f;
#pragma unroll
    for (int k = 0; k < 8; k++) { v[k] = src[lane + k * 32]; s += v[k]; }
#pragma unroll
    for (int o = 16; o; o >>= 1) s += __shfl_xor_sync(0xffffffffu, s, o);
    float mean = s * (1.f / 256.f);
    float vs = 0.f;
#pragma unroll
    for (int k = 0; k < 8; k++) { float t = v[k] - mean; vs += t * t; }
#pragma unroll
    for (int o = 16; o; o >>= 1) vs += __shfl_xor_sync(0xffffffffu, vs, o);
    float rstd = rsqrtf(vs * (1.f / 256.f) + 1e-5f);
    float* dst = out + ((size_t)warp << 8);
#pragma unroll
    for (int k = 0; k < 8; k++) {
        int c = lane + k * 32;
        dst[c] = (v[k] - mean) * rstd * g[c] + b[c];
    }
}

// ---------------------------------------------------------------------------
// Generic tiled SGEMM:  C[M,N] = (A[M,K] @ B[N,K]^T + bias) * alpha  (+res)(gelu)
// BM=BN=64, BK=16, 256 threads, 4x4 microtile per thread.
// flags: bit0 = exact gelu, bit1 = residual add (res, same layout as C)
// ---------------------------------------------------------------------------
__global__ void sgemm_kernel(const float* __restrict__ A,
                             const float* __restrict__ B,
                             const float* __restrict__ bias,
                             const float* __restrict__ res,
                             float* __restrict__ Cout,
                             int M, int N, int K, float alpha, int flags)
{
    __shared__ float As[16][65];
    __shared__ float Bs[16][68];   // row = 68 floats = 272B (16B aligned)

    int tid = threadIdx.x;
    int bm = blockIdx.y * 64, bn = blockIdx.x * 64;
    int lr = tid >> 2, lc = tid & 3;
    int ty = tid >> 4, tx = tid & 15;

    float acc[4][4] = {};
    const float* Ap = A + (size_t)(bm + lr) * K + lc * 4;
    const float* Bp = B + (size_t)(bn + lr) * K + lc * 4;

    for (int k0 = 0; k0 < K; k0 += 16) {
        float4 a4 = *(const float4*)(Ap + k0);
        float4 b4 = *(const float4*)(Bp + k0);
        __syncthreads();
        As[lc * 4 + 0][lr] = a4.x; As[lc * 4 + 1][lr] = a4.y;
        As[lc * 4 + 2][lr] = a4.z; As[lc * 4 + 3][lr] = a4.w;
        Bs[lc * 4 + 0][lr] = b4.x; Bs[lc * 4 + 1][lr] = b4.y;
        Bs[lc * 4 + 2][lr] = b4.z; Bs[lc * 4 + 3][lr] = b4.w;
        __syncthreads();
#pragma unroll
        for (int k = 0; k < 16; k++) {
            float4 rb = *(const float4*)&Bs[k][tx * 4];
            float ra0 = As[k][ty * 4 + 0];
            float ra1 = As[k][ty * 4 + 1];
            float ra2 = As[k][ty * 4 + 2];
            float ra3 = As[k][ty * 4 + 3];
            acc[0][0] += ra0 * rb.x; acc[0][1] += ra0 * rb.y;
            acc[0][2] += ra0 * rb.z; acc[0][3] += ra0 * rb.w;
            acc[1][0] += ra1 * rb.x; acc[1][1] += ra1 * rb.y;
            acc[1][2] += ra1 * rb.z; acc[1][3] += ra1 * rb.w;
            acc[2][0] += ra2 * rb.x; acc[2][1] += ra2 * rb.y;
            acc[2][2] += ra2 * rb.z; acc[2][3] += ra2 * rb.w;
            acc[3][0] += ra3 * rb.x; acc[3][1] += ra3 * rb.y;
            acc[3][2] += ra3 * rb.z; acc[3][3] += ra3 * rb.w;
        }
    }

#pragma unroll
    for (int i = 0; i < 4; i++) {
        int row = bm + ty * 4 + i;
#pragma unroll
        for (int j = 0; j < 4; j++) {
            int col = bn + tx * 4 + j;
            float v = (acc[i][j] + bias[col]) * alpha;
            if (flags & 1) v = 0.5f * v * (1.f + erff(v * 0.70710678118654752f));
            if (flags & 2) v += res[(size_t)row * N + col];
            Cout[(size_t)row * N + col] = v;
        }
    }
}

// ---------------------------------------------------------------------------
// K4: windowed attention. One block per (window, head): 2048*8 = 16384 blocks.
// S = q k^T + rel_bias + mask ; softmax rows ; O = S v
// ---------------------------------------------------------------------------
__global__ void attn_kernel(const float* __restrict__ Q,
                            const float* __restrict__ KV,
                            const float* __restrict__ bt,    // [225][8]
                            const float* __restrict__ mask,  // [1024][64][64]
                            float* __restrict__ AO)
{
    __shared__ float qs[64][33], ks[64][33], vsm[64][33];
    __shared__ float Ss[64][65];

    int blk = blockIdx.x;
    int wi = blk >> 3, head = blk & 7;
    int tid = threadIdx.x;
    size_t qbase  = (size_t)wi * 64 * 256 + head * 32;
    size_t kvbase = (size_t)wi * 64 * 512 + head * 32;

    for (int idx = tid; idx < 2048; idx += 256) {
        int n = idx >> 5, dd = idx & 31;
        qs[n][dd]  = Q [qbase  + (size_t)n * 256 + dd];
        ks[n][dd]  = KV[kvbase + (size_t)n * 512 + dd];
        vsm[n][dd] = KV[kvbase + (size_t)n * 512 + 256 + dd];
    }
    __syncthreads();

    // S = q k^T, 4x4 microtile per thread
    int n0 = (tid >> 4) * 4, m0 = (tid & 15) * 4;
    float acc[4][4] = {};
#pragma unroll
    for (int dd = 0; dd < 32; dd++) {
        float qa[4], kb[4];
#pragma unroll
        for (int i = 0; i < 4; i++) qa[i] = qs[n0 + i][dd];
#pragma unroll
        for (int j = 0; j < 4; j++) kb[j] = ks[m0 + j][dd];
#pragma unroll
        for (int i = 0; i < 4; i++)
#pragma unroll
            for (int j = 0; j < 4; j++) acc[i][j] += qa[i] * kb[j];
    }

    const float* mrow = mask + (size_t)(wi & 1023) * 4096;
#pragma unroll
    for (int i = 0; i < 4; i++) {
        int n = n0 + i; int i1 = n >> 3, j1 = n & 7;
#pragma unroll
        for (int j = 0; j < 4; j++) {
            int m = m0 + j; int i2 = m >> 3, j2 = m & 7;
            int ridx = (i1 - i2 + 7) * 15 + (j1 - j2 + 7);
            Ss[n][m] = acc[i][j] + bt[ridx * 8 + head] + mrow[n * 64 + m];
        }
    }
    __syncthreads();

    // softmax: 4 threads per row (lanes aligned within warp)
    int row = tid >> 2, q4 = tid & 3;
    float mx = -1e30f;
    for (int m = q4; m < 64; m += 4) mx = fmaxf(mx, Ss[row][m]);
    mx = fmaxf(mx, __shfl_xor_sync(0xffffffffu, mx, 1));
    mx = fmaxf(mx, __shfl_xor_sync(0xffffffffu, mx, 2));
    float sum = 0.f;
    for (int m = q4; m < 64; m += 4) {
        float e = __expf(Ss[row][m] - mx); Ss[row][m] = e; sum += e;
    }
    sum += __shfl_xor_sync(0xffffffffu, sum, 1);
    sum += __shfl_xor_sync(0xffffffffu, sum, 2);
    float inv = 1.f / sum;
    for (int m = q4; m < 64; m += 4) Ss[row][m] *= inv;
    __syncthreads();

    // O = S @ v : thread -> (row, 8 head-dims)
    int dg = q4 * 8;
    float o[8] = {};
    for (int m = 0; m < 64; m++) {
        float s = Ss[row][m];
#pragma unroll
        for (int i = 0; i < 8; i++) o[i] += s * vsm[m][dg + i];
    }
    float* dst = AO + (size_t)(wi * 64 + row) * 256 + head * 32 + dg;
#pragma unroll
    for (int i = 0; i < 8; i++) dst[i] = o[i];
}

// ---------------------------------------------------------------------------
// K6: window reverse + roll(+4,+4) + residual with x[:,0]. One warp per row.
// ---------------------------------------------------------------------------
__global__ void reverse_residual_kernel(const float* __restrict__ x,
                                        const float* __restrict__ po,
                                        float* __restrict__ x1)
{
    int warp = (blockIdx.x * blockDim.x + threadIdx.x) >> 5;
    int lane = threadIdx.x & 31;
    int bb = warp >> 16, hw = warp & 65535;
    int h = hw >> 8, w = hw & 255;
    int hp = (h - 4) & 255, wp = (w - 4) & 255;   // inverse of roll(+4)
    int wh = hp >> 3, i = hp & 7, wc = wp >> 3, j = wp & 7;
    int wi = bb * 1024 + wh * 32 + wc, n = i * 8 + j;
    const float* xs = x  + ((size_t)(bb * 2) * 65536 + hw) * 256;      // x[b,0,h,w,:]
    const float* ps = po + (size_t)(wi * 64 + n) * 256;
    float* dst = x1 + ((size_t)warp << 8);
#pragma unroll
    for (int k = 0; k < 8; k++) {
        int c = lane + k * 32;
        dst[c] = xs[c] + ps[c];
    }
}

// ---------------------------------------------------------------------------
extern "C" void kernel_launch(void* const* d_in, const int* in_sizes, int n_in,
                              void* d_out, int out_size)
{
    const float* x   = (const float*)d_in[0];
    const float* mask= (const float*)d_in[1];
    const float* g1  = (const float*)d_in[2];
    const float* b1  = (const float*)d_in[3];
    const float* qw  = (const float*)d_in[4];
    const float* qb  = (const float*)d_in[5];
    const float* kvw = (const float*)d_in[6];
    const float* kvb = (const float*)d_in[7];
    const float* pw  = (const float*)d_in[8];
    const float* pb  = (const float*)d_in[9];
    const float* bt  = (const float*)d_in[10];
    const float* g2  = (const float*)d_in[11];
    const float* b2  = (const float*)d_in[12];
    const float* w1  = (const float*)d_in[13];
    const float* bi1 = (const float*)d_in[14];
    const float* w2  = (const float*)d_in[15];
    const float* bi2 = (const float*)d_in[16];
    float* out = (float*)d_out;

    float *qin, *kvin, *q, *kv, *ao, *po, *x1, *x1n, *h;
    cudaGetSymbolAddress((void**)&qin,  g_qin);
    cudaGetSymbolAddress((void**)&kvin, g_kvin);
    cudaGetSymbolAddress((void**)&q,    g_q);
    cudaGetSymbolAddress((void**)&kv,   g_kv);
    cudaGetSymbolAddress((void**)&ao,   g_ao);
    cudaGetSymbolAddress((void**)&po,   g_po);
    cudaGetSymbolAddress((void**)&x1,   g_x1);
    cudaGetSymbolAddress((void**)&x1n,  g_x1n);
    cudaGetSymbolAddress((void**)&h,    g_h);

    // K1: LN1 + shift + window partition (both depth slices)
    ln_window_kernel<<<32768, 256>>>(x, g1, b1, qin, kvin);
    // K2: q = (q_in @ qw^T + qb) * d^-0.5
    sgemm_kernel<<<dim3(4, 2048), 256>>>(qin, qw, qb, nullptr, q,
                                         MROWS, 256, 256, 0.17677669529663687f, 0);
    // K3: kv = kv_in @ kvw^T + kvb
    sgemm_kernel<<<dim3(8, 2048), 256>>>(kvin, kvw, kvb, nullptr, kv,
                                         MROWS, 512, 256, 1.f, 0);
    // K4: windowed attention
    attn_kernel<<<16384, 256>>>(q, kv, bt, mask, ao);
    // K5: proj + residual(q_in)
    sgemm_kernel<<<dim3(4, 2048), 256>>>(ao, pw, pb, qin, po,
                                         MROWS, 256, 256, 1.f, 2);
    // K6: window reverse + roll + residual with x[:,0]
    reverse_residual_kernel<<<16384, 256>>>(x, po, x1);
    // K7: LN2
    ln_rows_kernel<<<16384, 256>>>(x1, g2, b2, x1n);
    // K8: MLP up + exact gelu
    sgemm_kernel<<<dim3(16, 2048), 256>>>(x1n, w1, bi1, nullptr, h,
                                          MROWS, HID, 256, 1.f, 1);
    // K9: MLP down + residual(x1) -> final output
    sgemm_kernel<<<dim3(4, 2048), 256>>>(h, w2, bi2, x1, out,
                                         MROWS, 256, HID, 1.f, 2);
}

// round 4
// speedup vs baseline: 1.0007x; 1.0007x over previous
#include <cuda_runtime.h>
#include <cstdint>
#include <math.h>

// ---------------------------------------------------------------------------
// Swin-style block:
//  LN1 -> shift(-4,-4) -> 8x8 window partition (q from D=0, kv from D=1)
//  q/kv projections -> windowed MHA (8 heads, d=32, rel-pos bias + mask)
//  -> proj + residual(q_in) -> window reverse -> shift(+4,+4) -> +x[:,0]
//  -> LN2 -> MLP (C->4C gelu -> C) -> residual
// All fp32. Staged kernels with static __device__ scratch.
// ---------------------------------------------------------------------------

#define MROWS 131072          // B*nwin*N = 2*1024*64 tokens
#define HID   1024

__device__ float g_qin [(size_t)MROWS * 256];
__device__ float g_kvin[(size_t)MROWS * 256];
__device__ float g_q   [(size_t)MROWS * 256];
__device__ float g_kv  [(size_t)MROWS * 512];
__device__ float g_ao  [(size_t)MROWS * 256];
__device__ float g_po  [(size_t)MROWS * 256];
__device__ float g_x1  [(size_t)MROWS * 256];
__device__ float g_x1n [(size_t)MROWS * 256];
__device__ float g_h   [(size_t)MROWS * HID];

// ---------------------------------------------------------------------------
// K1: LayerNorm + shift + window partition. One warp per output row.
// warp id = d*131072 + (wi*64 + n);   d=0 -> q_in, d=1 -> kv_in
// ---------------------------------------------------------------------------
__global__ void ln_window_kernel(const float* __restrict__ x,
                                 const float* __restrict__ g,
                                 const float* __restrict__ b,
                                 float* __restrict__ qin,
                                 float* __restrict__ kvin)
{
    int warp = (blockIdx.x * blockDim.x + threadIdx.x) >> 5;
    int lane = threadIdx.x & 31;
    int d  = warp >> 17;
    int r  = warp & 131071;
    int wi = r >> 6, n = r & 63;
    int bb = wi >> 10, wl = wi & 1023;
    int wh = wl >> 5,  wc = wl & 31;
    int i  = n >> 3,   j  = n & 7;
    int hs = (wh * 8 + i + 4) & 255;   // roll(-4)
    int ws = (wc * 8 + j + 4) & 255;
    const float* src = x + ((((size_t)(bb * 2 + d) * 256 + hs) * 256 + ws) << 8);

    float v[8]; float s = 0.f;
#pragma unroll
    for (int k = 0; k < 8; k++) { v[k] = src[lane + k * 32]; s += v[k]; }
#pragma unroll
    for (int o = 16; o; o >>= 1) s += __shfl_xor_sync(0xffffffffu, s, o);
    float mean = s * (1.f / 256.f);
    float vs = 0.f;
#pragma unroll
    for (int k = 0; k < 8; k++) { float t = v[k] - mean; vs += t * t; }
#pragma unroll
    for (int o = 16; o; o >>= 1) vs += __shfl_xor_sync(0xffffffffu, vs, o);
    float rstd = rsqrtf(vs * (1.f / 256.f) + 1e-5f);

    float* dst = (d == 0 ? qin : kvin) + ((size_t)r << 8);
#pragma unroll
    for (int k = 0; k < 8; k++) {
        int c = lane + k * 32;
        dst[c] = (v[k] - mean) * rstd * g[c] + b[c];
    }
}

// ---------------------------------------------------------------------------
// Plain row LayerNorm (for LN2 on x1). One warp per row, 131072 rows.
// ---------------------------------------------------------------------------
__global__ void ln_rows_kernel(const float* __restrict__ in,
                               const float* __restrict__ g,
                               const float* __restrict__ b,
                               float* __restrict__ out)
{
    int warp = (blockIdx.x * blockDim.x + threadIdx.x) >> 5;
    int lane = threadIdx.x & 31;
    const float* src = in + ((size_t)warp << 8);
    float v[8]; float s = 0.f;
#pragma unroll
    for (int k = 0; k < 8; k++) { v[k] = src[lane + k * 32]; s += v[k]; }
#pragma unroll
    for (int o = 16; o; o >>= 1) s += __shfl_xor_sync(0xffffffffu, s, o);
    float mean = s * (1.f / 256.f);
    float vs = 0.f;
#pragma unroll
    for (int k = 0; k < 8; k++) { float t = v[k] - mean; vs += t * t; }
#pragma unroll
    for (int o = 16; o; o >>= 1) vs += __shfl_xor_sync(0xffffffffu, vs, o);
    float rstd = rsqrtf(vs * (1.f / 256.f) + 1e-5f);
    float* dst = out + ((size_t)warp << 8);
#pragma unroll
    for (int k = 0; k < 8; k++) {
        int c = lane + k * 32;
        dst[c] = (v[k] - mean) * rstd * g[c] + b[c];
    }
}

// ---------------------------------------------------------------------------
// Generic tiled SGEMM:  C[M,N] = (A[M,K] @ B[N,K]^T + bias) * alpha  (+res)(gelu)
// BM=BN=64, BK=16, 256 threads, 4x4 microtile per thread.
// flags: bit0 = exact gelu, bit1 = residual add (res, same layout as C)
// ---------------------------------------------------------------------------
__global__ void sgemm_kernel(const float* __restrict__ A,
                             const float* __restrict__ B,
                             const float* __restrict__ bias,
                             const float* __restrict__ res,
                             float* __restrict__ Cout,
                             int M, int N, int K, float alpha, int flags)
{
    __shared__ float As[16][65];
    __shared__ float Bs[16][68];   // row = 68 floats = 272B (16B aligned)

    int tid = threadIdx.x;
    int bm = blockIdx.y * 64, bn = blockIdx.x * 64;
    int lr = tid >> 2, lc = tid & 3;
    int ty = tid >> 4, tx = tid & 15;

    float acc[4][4] = {};
    const float* Ap = A + (size_t)(bm + lr) * K + lc * 4;
    const float* Bp = B + (size_t)(bn + lr) * K + lc * 4;

    for (int k0 = 0; k0 < K; k0 += 16) {
        float4 a4 = *(const float4*)(Ap + k0);
        float4 b4 = *(const float4*)(Bp + k0);
        __syncthreads();
        As[lc * 4 + 0][lr] = a4.x; As[lc * 4 + 1][lr] = a4.y;
        As[lc * 4 + 2][lr] = a4.z; As[lc * 4 + 3][lr] = a4.w;
        Bs[lc * 4 + 0][lr] = b4.x; Bs[lc * 4 + 1][lr] = b4.y;
        Bs[lc * 4 + 2][lr] = b4.z; Bs[lc * 4 + 3][lr] = b4.w;
        __syncthreads();
#pragma unroll
        for (int k = 0; k < 16; k++) {
            float4 rb = *(const float4*)&Bs[k][tx * 4];
            float ra0 = As[k][ty * 4 + 0];
            float ra1 = As[k][ty * 4 + 1];
            float ra2 = As[k][ty * 4 + 2];
            float ra3 = As[k][ty * 4 + 3];
            acc[0][0] += ra0 * rb.x; acc[0][1] += ra0 * rb.y;
            acc[0][2] += ra0 * rb.z; acc[0][3] += ra0 * rb.w;
            acc[1][0] += ra1 * rb.x; acc[1][1] += ra1 * rb.y;
            acc[1][2] += ra1 * rb.z; acc[1][3] += ra1 * rb.w;
            acc[2][0] += ra2 * rb.x; acc[2][1] += ra2 * rb.y;
            acc[2][2] += ra2 * rb.z; acc[2][3] += ra2 * rb.w;
            acc[3][0] += ra3 * rb.x; acc[3][1] += ra3 * rb.y;
            acc[3][2] += ra3 * rb.z; acc[3][3] += ra3 * rb.w;
        }
    }

#pragma unroll
    for (int i = 0; i < 4; i++) {
        int row = bm + ty * 4 + i;
#pragma unroll
        for (int j = 0; j < 4; j++) {
            int col = bn + tx * 4 + j;
            float v = (acc[i][j] + bias[col]) * alpha;
            if (flags & 1) v = 0.5f * v * (1.f + erff(v * 0.70710678118654752f));
            if (flags & 2) v += res[(size_t)row * N + col];
            Cout[(size_t)row * N + col] = v;
        }
    }
}

// ---------------------------------------------------------------------------
// K4: windowed attention. One block per (window, head): 2048*8 = 16384 blocks.
// S = q k^T + rel_bias + mask ; softmax rows ; O = S v
// ---------------------------------------------------------------------------
__global__ void attn_kernel(const float* __restrict__ Q,
                            const float* __restrict__ KV,
                            const float* __restrict__ bt,    // [225][8]
                            const float* __restrict__ mask,  // [1024][64][64]
                            float* __restrict__ AO)
{
    __shared__ float qs[64][33], ks[64][33], vsm[64][33];
    __shared__ float Ss[64][65];

    int blk = blockIdx.x;
    int wi = blk >> 3, head = blk & 7;
    int tid = threadIdx.x;
    size_t qbase  = (size_t)wi * 64 * 256 + head * 32;
    size_t kvbase = (size_t)wi * 64 * 512 + head * 32;

    for (int idx = tid; idx < 2048; idx += 256) {
        int n = idx >> 5, dd = idx & 31;
        qs[n][dd]  = Q [qbase  + (size_t)n * 256 + dd];
        ks[n][dd]  = KV[kvbase + (size_t)n * 512 + dd];
        vsm[n][dd] = KV[kvbase + (size_t)n * 512 + 256 + dd];
    }
    __syncthreads();

    // S = q k^T, 4x4 microtile per thread
    int n0 = (tid >> 4) * 4, m0 = (tid & 15) * 4;
    float acc[4][4] = {};
#pragma unroll
    for (int dd = 0; dd < 32; dd++) {
        float qa[4], kb[4];
#pragma unroll
        for (int i = 0; i < 4; i++) qa[i] = qs[n0 + i][dd];
#pragma unroll
        for (int j = 0; j < 4; j++) kb[j] = ks[m0 + j][dd];
#pragma unroll
        for (int i = 0; i < 4; i++)
#pragma unroll
            for (int j = 0; j < 4; j++) acc[i][j] += qa[i] * kb[j];
    }

    const float* mrow = mask + (size_t)(wi & 1023) * 4096;
#pragma unroll
    for (int i = 0; i < 4; i++) {
        int n = n0 + i; int i1 = n >> 3, j1 = n & 7;
#pragma unroll
        for (int j = 0; j < 4; j++) {
            int m = m0 + j; int i2 = m >> 3, j2 = m & 7;
            int ridx = (i1 - i2 + 7) * 15 + (j1 - j2 + 7);
            Ss[n][m] = acc[i][j] + bt[ridx * 8 + head] + mrow[n * 64 + m];
        }
    }
    __syncthreads();

    // softmax: 4 threads per row (lanes aligned within warp)
    int row = tid >> 2, q4 = tid & 3;
    float mx = -1e30f;
    for (int m = q4; m < 64; m += 4) mx = fmaxf(mx, Ss[row][m]);
    mx = fmaxf(mx, __shfl_xor_sync(0xffffffffu, mx, 1));
    mx = fmaxf(mx, __shfl_xor_sync(0xffffffffu, mx, 2));
    float sum = 0.f;
    for (int m = q4; m < 64; m += 4) {
        float e = __expf(Ss[row][m] - mx); Ss[row][m] = e; sum += e;
    }
    sum += __shfl_xor_sync(0xffffffffu, sum, 1);
    sum += __shfl_xor_sync(0xffffffffu, sum, 2);
    float inv = 1.f / sum;
    for (int m = q4; m < 64; m += 4) Ss[row][m] *= inv;
    __syncthreads();

    // O = S @ v : thread -> (row, 8 head-dims)
    int dg = q4 * 8;
    float o[8] = {};
    for (int m = 0; m < 64; m++) {
        float s = Ss[row][m];
#pragma unroll
        for (int i = 0; i < 8; i++) o[i] += s * vsm[m][dg + i];
    }
    float* dst = AO + (size_t)(wi * 64 + row) * 256 + head * 32 + dg;
#pragma unroll
    for (int i = 0; i < 8; i++) dst[i] = o[i];
}

// ---------------------------------------------------------------------------
// K6: window reverse + roll(+4,+4) + residual with x[:,0]. One warp per row.
// ---------------------------------------------------------------------------
__global__ void reverse_residual_kernel(const float* __restrict__ x,
                                        const float* __restrict__ po,
                                        float* __restrict__ x1)
{
    int warp = (blockIdx.x * blockDim.x + threadIdx.x) >> 5;
    int lane = threadIdx.x & 31;
    int bb = warp >> 16, hw = warp & 65535;
    int h = hw >> 8, w = hw & 255;
    int hp = (h - 4) & 255, wp = (w - 4) & 255;   // inverse of roll(+4)
    int wh = hp >> 3, i = hp & 7, wc = wp >> 3, j = wp & 7;
    int wi = bb * 1024 + wh * 32 + wc, n = i * 8 + j;
    const float* xs = x  + ((size_t)(bb * 2) * 65536 + hw) * 256;      // x[b,0,h,w,:]
    const float* ps = po + (size_t)(wi * 64 + n) * 256;
    float* dst = x1 + ((size_t)warp << 8);
#pragma unroll
    for (int k = 0; k < 8; k++) {
        int c = lane + k * 32;
        dst[c] = xs[c] + ps[c];
    }
}

// ---------------------------------------------------------------------------
extern "C" void kernel_launch(void* const* d_in, const int* in_sizes, int n_in,
                              void* d_out, int out_size)
{
    const float* x   = (const float*)d_in[0];
    const float* mask= (const float*)d_in[1];
    const float* g1  = (const float*)d_in[2];
    const float* b1  = (const float*)d_in[3];
    const float* qw  = (const float*)d_in[4];
    const float* qb  = (const float*)d_in[5];
    const float* kvw = (const float*)d_in[6];
    const float* kvb = (const float*)d_in[7];
    const float* pw  = (const float*)d_in[8];
    const float* pb  = (const float*)d_in[9];
    const float* bt  = (const float*)d_in[10];
    const float* g2  = (const float*)d_in[11];
    const float* b2  = (const float*)d_in[12];
    const float* w1  = (const float*)d_in[13];
    const float* bi1 = (const float*)d_in[14];
    const float* w2  = (const float*)d_in[15];
    const float* bi2 = (const float*)d_in[16];
    float* out = (float*)d_out;

    float *qin, *kvin, *q, *kv, *ao, *po, *x1, *x1n, *h;
    cudaGetSymbolAddress((void**)&qin,  g_qin);
    cudaGetSymbolAddress((void**)&kvin, g_kvin);
    cudaGetSymbolAddress((void**)&q,    g_q);
    cudaGetSymbolAddress((void**)&kv,   g_kv);
    cudaGetSymbolAddress((void**)&ao,   g_ao);
    cudaGetSymbolAddress((void**)&po,   g_po);
    cudaGetSymbolAddress((void**)&x1,   g_x1);
    cudaGetSymbolAddress((void**)&x1n,  g_x1n);
    cudaGetSymbolAddress((void**)&h,    g_h);

    // K1: LN1 + shift + window partition (both depth slices)
    ln_window_kernel<<<32768, 256>>>(x, g1, b1, qin, kvin);
    // K2: q = (q_in @ qw^T + qb) * d^-0.5
    sgemm_kernel<<<dim3(4, 2048), 256>>>(qin, qw, qb, nullptr, q,
                                         MROWS, 256, 256, 0.17677669529663687f, 0);
    // K3: kv = kv_in @ kvw^T + kvb
    sgemm_kernel<<<dim3(8, 2048), 256>>>(kvin, kvw, kvb, nullptr, kv,
                                         MROWS, 512, 256, 1.f, 0);
    // K4: windowed attention
    attn_kernel<<<16384, 256>>>(q, kv, bt, mask, ao);
    // K5: proj + residual(q_in)
    sgemm_kernel<<<dim3(4, 2048), 256>>>(ao, pw, pb, qin, po,
                                         MROWS, 256, 256, 1.f, 2);
    // K6: window reverse + roll + residual with x[:,0]
    reverse_residual_kernel<<<16384, 256>>>(x, po, x1);
    // K7: LN2
    ln_rows_kernel<<<16384, 256>>>(x1, g2, b2, x1n);
    // K8: MLP up + exact gelu
    sgemm_kernel<<<dim3(16, 2048), 256>>>(x1n, w1, bi1, nullptr, h,
                                          MROWS, HID, 256, 1.f, 1);
    // K9: MLP down + residual(x1) -> final output
    sgemm_kernel<<<dim3(4, 2048), 256>>>(h, w2, bi2, x1, out,
                                         MROWS, 256, HID, 1.f, 2);
}

// round 5
// speedup vs baseline: 3.1619x; 3.1596x over previous
#include <cuda_runtime.h>
#include <cuda_bf16.h>
#include <cstdint>
#include <math.h>

// ---------------------------------------------------------------------------
// Swin-style block, GEMMs on tensor cores (mma.sync bf16 -> fp32 acc).
// Residuals / softmax / LN / GELU stay fp32.
// ---------------------------------------------------------------------------

#define MROWS 131072          // B*nwin*N = 2*1024*64 tokens
#define HID   1024

typedef __nv_bfloat16 bf16;

__device__ float g_qin [(size_t)MROWS * 256];   // fp32 (K5 residual)
__device__ bf16  g_qinb[(size_t)MROWS * 256];   // bf16 GEMM operand
__device__ bf16  g_kvinb[(size_t)MROWS * 256];
__device__ float g_q   [(size_t)MROWS * 256];
__device__ float g_kv  [(size_t)MROWS * 512];
__device__ bf16  g_aob [(size_t)MROWS * 256];
__device__ float g_po  [(size_t)MROWS * 256];
__device__ float g_x1  [(size_t)MROWS * 256];
__device__ bf16  g_x1nb[(size_t)MROWS * 256];
__device__ bf16  g_hb  [(size_t)MROWS * HID];
__device__ bf16  g_wb  [786432];                // qw|kvw|pw|w1|w2 in bf16

// ---------------------------------------------------------------------------
// fp32 -> bf16 weight convert (n divisible by 4)
// ---------------------------------------------------------------------------
__global__ void f2b_kernel(const float* __restrict__ s, bf16* __restrict__ d, int n)
{
    int i = blockIdx.x * blockDim.x + threadIdx.x;
    if (i * 4 < n) {
        float4 v = *(const float4*)(s + i * 4);
        __nv_bfloat162* dp = (__nv_bfloat162*)(d + i * 4);
        dp[0] = __floats2bfloat162_rn(v.x, v.y);
        dp[1] = __floats2bfloat162_rn(v.z, v.w);
    }
}

// ---------------------------------------------------------------------------
// K1: LN1 + shift(-4,-4) + window partition. One warp per row.
// d=0 -> qin (fp32 + bf16), d=1 -> kvin (bf16)
// ---------------------------------------------------------------------------
__global__ void ln_window_kernel(const float* __restrict__ x,
                                 const float* __restrict__ g,
                                 const float* __restrict__ b,
                                 float* __restrict__ qin,
                                 bf16* __restrict__ qinb,
                                 bf16* __restrict__ kvinb)
{
    int warp = (blockIdx.x * blockDim.x + threadIdx.x) >> 5;
    int lane = threadIdx.x & 31;
    int d  = warp >> 17;
    int r  = warp & 131071;
    int wi = r >> 6, n = r & 63;
    int bb = wi >> 10, wl = wi & 1023;
    int wh = wl >> 5,  wc = wl & 31;
    int i  = n >> 3,   j  = n & 7;
    int hs = (wh * 8 + i + 4) & 255;   // roll(-4)
    int ws = (wc * 8 + j + 4) & 255;
    const float* src = x + ((((size_t)(bb * 2 + d) * 256 + hs) * 256 + ws) << 8);

    float v[8]; float s = 0.f;
#pragma unroll
    for (int k = 0; k < 8; k++) { v[k] = src[lane + k * 32]; s += v[k]; }
#pragma unroll
    for (int o = 16; o; o >>= 1) s += __shfl_xor_sync(0xffffffffu, s, o);
    float mean = s * (1.f / 256.f);
    float vs = 0.f;
#pragma unroll
    for (int k = 0; k < 8; k++) { float t = v[k] - mean; vs += t * t; }
#pragma unroll
    for (int o = 16; o; o >>= 1) vs += __shfl_xor_sync(0xffffffffu, vs, o);
    float rstd = rsqrtf(vs * (1.f / 256.f) + 1e-5f);

    if (d == 0) {
        float* df = qin + ((size_t)r << 8);
        bf16*  db = qinb + ((size_t)r << 8);
#pragma unroll
        for (int k = 0; k < 8; k++) {
            int c = lane + k * 32;
            float y = (v[k] - mean) * rstd * g[c] + b[c];
            df[c] = y; db[c] = __float2bfloat16(y);
        }
    } else {
        bf16* db = kvinb + ((size_t)r << 8);
#pragma unroll
        for (int k = 0; k < 8; k++) {
            int c = lane + k * 32;
            db[c] = __float2bfloat16((v[k] - mean) * rstd * g[c] + b[c]);
        }
    }
}

// ---------------------------------------------------------------------------
// LN2 rows -> bf16 output. One warp per row.
// ---------------------------------------------------------------------------
__global__ void ln_rows_kernel(const float* __restrict__ in,
                               const float* __restrict__ g,
                               const float* __restrict__ b,
                               bf16* __restrict__ out)
{
    int warp = (blockIdx.x * blockDim.x + threadIdx.x) >> 5;
    int lane = threadIdx.x & 31;
    const float* src = in + ((size_t)warp << 8);
    float v[8]; float s = 0.f;
#pragma unroll
    for (int k = 0; k < 8; k++) { v[k] = src[lane + k * 32]; s += v[k]; }
#pragma unroll
    for (int o = 16; o; o >>= 1) s += __shfl_xor_sync(0xffffffffu, s, o);
    float mean = s * (1.f / 256.f);
    float vs = 0.f;
#pragma unroll
    for (int k = 0; k < 8; k++) { float t = v[k] - mean; vs += t * t; }
#pragma unroll
    for (int o = 16; o; o >>= 1) vs += __shfl_xor_sync(0xffffffffu, vs, o);
    float rstd = rsqrtf(vs * (1.f / 256.f) + 1e-5f);
    bf16* dst = out + ((size_t)warp << 8);
#pragma unroll
    for (int k = 0; k < 8; k++) {
        int c = lane + k * 32;
        dst[c] = __float2bfloat16((v[k] - mean) * rstd * g[c] + b[c]);
    }
}

// ---------------------------------------------------------------------------
// bf16 tensor-core GEMM: C[M,N] = (A[M,K] @ B[N,K]^T + bias)*alpha (gelu)(+res)
// BM=128, BN=128, BK=32, 256 threads (8 warps, warp tile 64x32).
// flags: bit0 = exact gelu, bit1 = residual add (fp32, layout of C)
// Cf (fp32) and/or Cb (bf16) outputs.
// ---------------------------------------------------------------------------
__device__ __forceinline__ void mma16816(float* d, const uint32_t* a, const uint32_t* b)
{
    asm volatile(
        "mma.sync.aligned.m16n8k16.row.col.f32.bf16.bf16.f32 "
        "{%0,%1,%2,%3}, {%4,%5,%6,%7}, {%8,%9}, {%0,%1,%2,%3};\n"
        : "+f"(d[0]), "+f"(d[1]), "+f"(d[2]), "+f"(d[3])
        : "r"(a[0]), "r"(a[1]), "r"(a[2]), "r"(a[3]), "r"(b[0]), "r"(b[1]));
}

#define SPITCH 40   // bf16 elements per smem row (bank-conflict-free for frags)

__global__ void __launch_bounds__(256) bgemm_kernel(
    const bf16* __restrict__ A,
    const bf16* __restrict__ B,
    const float* __restrict__ bias,
    const float* __restrict__ res,
    float* __restrict__ Cf,
    bf16* __restrict__ Cb,
    int M, int N, int K, float alpha, int flags)
{
    __shared__ bf16 As[128 * SPITCH];
    __shared__ bf16 Bs[128 * SPITCH];

    int tid = threadIdx.x;
    int bm = blockIdx.y * 128, bn = blockIdx.x * 128;
    int lane = tid & 31, warp = tid >> 5;
    int wm = (warp >> 2) * 64, wn = (warp & 3) * 32;
    int g = lane >> 2, c4 = lane & 3;

    float acc[4][4][4] = {};

    int lr = tid >> 2;              // 0..63
    int kc = (tid & 3) * 8;         // 0,8,16,24
    const bf16* Ag  = A + (size_t)(bm + lr) * K + kc;
    const bf16* Ag2 = Ag + (size_t)64 * K;
    const bf16* Bg  = B + (size_t)(bn + lr) * K + kc;
    const bf16* Bg2 = Bg + (size_t)64 * K;

    for (int k0 = 0; k0 < K; k0 += 32) {
        uint4 av0 = *(const uint4*)(Ag  + k0);
        uint4 av1 = *(const uint4*)(Ag2 + k0);
        uint4 bv0 = *(const uint4*)(Bg  + k0);
        uint4 bv1 = *(const uint4*)(Bg2 + k0);
        __syncthreads();
        {
            uint2* d0 = (uint2*)(As + lr * SPITCH + kc);
            d0[0] = make_uint2(av0.x, av0.y); d0[1] = make_uint2(av0.z, av0.w);
            uint2* d1 = (uint2*)(As + (lr + 64) * SPITCH + kc);
            d1[0] = make_uint2(av1.x, av1.y); d1[1] = make_uint2(av1.z, av1.w);
            uint2* e0 = (uint2*)(Bs + lr * SPITCH + kc);
            e0[0] = make_uint2(bv0.x, bv0.y); e0[1] = make_uint2(bv0.z, bv0.w);
            uint2* e1 = (uint2*)(Bs + (lr + 64) * SPITCH + kc);
            e1[0] = make_uint2(bv1.x, bv1.y); e1[1] = make_uint2(bv1.z, bv1.w);
        }
        __syncthreads();

#pragma unroll
        for (int ks = 0; ks < 32; ks += 16) {
            uint32_t af[4][4], bfr[4][2];
#pragma unroll
            for (int mi = 0; mi < 4; mi++) {
                const bf16* p = As + (wm + mi * 16 + g) * SPITCH + ks + c4 * 2;
                af[mi][0] = *(const uint32_t*)p;
                af[mi][1] = *(const uint32_t*)(p + 8 * SPITCH);
                af[mi][2] = *(const uint32_t*)(p + 8);
                af[mi][3] = *(const uint32_t*)(p + 8 * SPITCH + 8);
            }
#pragma unroll
            for (int nj = 0; nj < 4; nj++) {
                const bf16* p = Bs + (wn + nj * 8 + g) * SPITCH + ks + c4 * 2;
                bfr[nj][0] = *(const uint32_t*)p;
                bfr[nj][1] = *(const uint32_t*)(p + 8);
            }
#pragma unroll
            for (int mi = 0; mi < 4; mi++)
#pragma unroll
                for (int nj = 0; nj < 4; nj++)
                    mma16816(acc[mi][nj], af[mi], bfr[nj]);
        }
    }

    // epilogue
#pragma unroll
    for (int mi = 0; mi < 4; mi++) {
        int row0 = bm + wm + mi * 16 + g;
#pragma unroll
        for (int nj = 0; nj < 4; nj++) {
            int col0 = bn + wn + nj * 8 + c4 * 2;
            float bia0 = bias[col0], bia1 = bias[col0 + 1];
#pragma unroll
            for (int h = 0; h < 2; h++) {           // h=0: row0, h=1: row0+8
                int row = row0 + h * 8;
                float v0 = (acc[mi][nj][h * 2 + 0] + bia0) * alpha;
                float v1 = (acc[mi][nj][h * 2 + 1] + bia1) * alpha;
                if (flags & 1) {
                    v0 = 0.5f * v0 * (1.f + erff(v0 * 0.70710678118654752f));
                    v1 = 0.5f * v1 * (1.f + erff(v1 * 0.70710678118654752f));
                }
                if (flags & 2) {
                    const float* rp = res + (size_t)row * N + col0;
                    v0 += rp[0]; v1 += rp[1];
                }
                if (Cf) {
                    float* cp = Cf + (size_t)row * N + col0;
                    cp[0] = v0; cp[1] = v1;
                }
                if (Cb) {
                    *(__nv_bfloat162*)(Cb + (size_t)row * N + col0) =
                        __floats2bfloat162_rn(v0, v1);
                }
            }
        }
    }
}

// ---------------------------------------------------------------------------
// K4: windowed attention (fp32). One block per (window, head). Output bf16.
// ---------------------------------------------------------------------------
__global__ void attn_kernel(const float* __restrict__ Q,
                            const float* __restrict__ KV,
                            const float* __restrict__ bt,    // [225][8]
                            const float* __restrict__ mask,  // [1024][64][64]
                            bf16* __restrict__ AO)
{
    __shared__ float qs[64][33], ks[64][33], vsm[64][33];
    __shared__ float Ss[64][65];

    int blk = blockIdx.x;
    int wi = blk >> 3, head = blk & 7;
    int tid = threadIdx.x;
    size_t qbase  = (size_t)wi * 64 * 256 + head * 32;
    size_t kvbase = (size_t)wi * 64 * 512 + head * 32;

    for (int idx = tid; idx < 2048; idx += 256) {
        int n = idx >> 5, dd = idx & 31;
        qs[n][dd]  = Q [qbase  + (size_t)n * 256 + dd];
        ks[n][dd]  = KV[kvbase + (size_t)n * 512 + dd];
        vsm[n][dd] = KV[kvbase + (size_t)n * 512 + 256 + dd];
    }
    __syncthreads();

    int n0 = (tid >> 4) * 4, m0 = (tid & 15) * 4;
    float acc[4][4] = {};
#pragma unroll
    for (int dd = 0; dd < 32; dd++) {
        float qa[4], kb[4];
#pragma unroll
        for (int i = 0; i < 4; i++) qa[i] = qs[n0 + i][dd];
#pragma unroll
        for (int j = 0; j < 4; j++) kb[j] = ks[m0 + j][dd];
#pragma unroll
        for (int i = 0; i < 4; i++)
#pragma unroll
            for (int j = 0; j < 4; j++) acc[i][j] += qa[i] * kb[j];
    }

    const float* mrow = mask + (size_t)(wi & 1023) * 4096;
#pragma unroll
    for (int i = 0; i < 4; i++) {
        int n = n0 + i; int i1 = n >> 3, j1 = n & 7;
#pragma unroll
        for (int j = 0; j < 4; j++) {
            int m = m0 + j; int i2 = m >> 3, j2 = m & 7;
            int ridx = (i1 - i2 + 7) * 15 + (j1 - j2 + 7);
            Ss[n][m] = acc[i][j] + bt[ridx * 8 + head] + mrow[n * 64 + m];
        }
    }
    __syncthreads();

    int row = tid >> 2, q4 = tid & 3;
    float mx = -1e30f;
    for (int m = q4; m < 64; m += 4) mx = fmaxf(mx, Ss[row][m]);
    mx = fmaxf(mx, __shfl_xor_sync(0xffffffffu, mx, 1));
    mx = fmaxf(mx, __shfl_xor_sync(0xffffffffu, mx, 2));
    float sum = 0.f;
    for (int m = q4; m < 64; m += 4) {
        float e = __expf(Ss[row][m] - mx); Ss[row][m] = e; sum += e;
    }
    sum += __shfl_xor_sync(0xffffffffu, sum, 1);
    sum += __shfl_xor_sync(0xffffffffu, sum, 2);
    float inv = 1.f / sum;
    for (int m = q4; m < 64; m += 4) Ss[row][m] *= inv;
    __syncthreads();

    int dg = q4 * 8;
    float o[8] = {};
    for (int m = 0; m < 64; m++) {
        float s = Ss[row][m];
#pragma unroll
        for (int i = 0; i < 8; i++) o[i] += s * vsm[m][dg + i];
    }
    bf16* dst = AO + (size_t)(wi * 64 + row) * 256 + head * 32 + dg;
#pragma unroll
    for (int i = 0; i < 8; i++) dst[i] = __float2bfloat16(o[i]);
}

// ---------------------------------------------------------------------------
// K6: window reverse + roll(+4,+4) + residual with x[:,0]. One warp per row.
// ---------------------------------------------------------------------------
__global__ void reverse_residual_kernel(const float* __restrict__ x,
                                        const float* __restrict__ po,
                                        float* __restrict__ x1)
{
    int warp = (blockIdx.x * blockDim.x + threadIdx.x) >> 5;
    int lane = threadIdx.x & 31;
    int bb = warp >> 16, hw = warp & 65535;
    int h = hw >> 8, w = hw & 255;
    int hp = (h - 4) & 255, wp = (w - 4) & 255;
    int wh = hp >> 3, i = hp & 7, wc = wp >> 3, j = wp & 7;
    int wi = bb * 1024 + wh * 32 + wc, n = i * 8 + j;
    const float* xs = x  + ((size_t)(bb * 2) * 65536 + hw) * 256;
    const float* ps = po + (size_t)(wi * 64 + n) * 256;
    float* dst = x1 + ((size_t)warp << 8);
#pragma unroll
    for (int k = 0; k < 8; k++) {
        int c = lane + k * 32;
        dst[c] = xs[c] + ps[c];
    }
}

// ---------------------------------------------------------------------------
extern "C" void kernel_launch(void* const* d_in, const int* in_sizes, int n_in,
                              void* d_out, int out_size)
{
    const float* x   = (const float*)d_in[0];
    const float* mask= (const float*)d_in[1];
    const float* g1  = (const float*)d_in[2];
    const float* b1  = (const float*)d_in[3];
    const float* qw  = (const float*)d_in[4];
    const float* qb  = (const float*)d_in[5];
    const float* kvw = (const float*)d_in[6];
    const float* kvb = (const float*)d_in[7];
    const float* pw  = (const float*)d_in[8];
    const float* pb  = (const float*)d_in[9];
    const float* bt  = (const float*)d_in[10];
    const float* g2  = (const float*)d_in[11];
    const float* b2  = (const float*)d_in[12];
    const float* w1  = (const float*)d_in[13];
    const float* bi1 = (const float*)d_in[14];
    const float* w2  = (const float*)d_in[15];
    const float* bi2 = (const float*)d_in[16];
    float* out = (float*)d_out;

    float *qin, *q, *kv, *po, *x1;
    bf16 *qinb, *kvinb, *aob, *x1nb, *hb, *wb;
    cudaGetSymbolAddress((void**)&qin,   g_qin);
    cudaGetSymbolAddress((void**)&qinb,  g_qinb);
    cudaGetSymbolAddress((void**)&kvinb, g_kvinb);
    cudaGetSymbolAddress((void**)&q,     g_q);
    cudaGetSymbolAddress((void**)&kv,    g_kv);
    cudaGetSymbolAddress((void**)&aob,   g_aob);
    cudaGetSymbolAddress((void**)&po,    g_po);
    cudaGetSymbolAddress((void**)&x1,    g_x1);
    cudaGetSymbolAddress((void**)&x1nb,  g_x1nb);
    cudaGetSymbolAddress((void**)&hb,    g_hb);
    cudaGetSymbolAddress((void**)&wb,    g_wb);

    bf16* qwb  = wb;
    bf16* kvwb = wb + 65536;
    bf16* pwb  = wb + 196608;
    bf16* w1b  = wb + 262144;
    bf16* w2b  = wb + 524288;

    // W0: weight conversion to bf16
    f2b_kernel<<<64, 256>>>(qw,  qwb,  65536);
    f2b_kernel<<<128, 256>>>(kvw, kvwb, 131072);
    f2b_kernel<<<64, 256>>>(pw,  pwb,  65536);
    f2b_kernel<<<256, 256>>>(w1,  w1b,  262144);
    f2b_kernel<<<256, 256>>>(w2,  w2b,  262144);

    // K1: LN1 + shift + window partition
    ln_window_kernel<<<32768, 256>>>(x, g1, b1, qin, qinb, kvinb);
    // K2: q = (q_in @ qw^T + qb) * d^-0.5  (fp32 out)
    bgemm_kernel<<<dim3(2, 1024), 256>>>(qinb, qwb, qb, nullptr, q, nullptr,
                                         MROWS, 256, 256, 0.17677669529663687f, 0);
    // K3: kv = kv_in @ kvw^T + kvb  (fp32 out)
    bgemm_kernel<<<dim3(4, 1024), 256>>>(kvinb, kvwb, kvb, nullptr, kv, nullptr,
                                         MROWS, 512, 256, 1.f, 0);
    // K4: windowed attention (bf16 out)
    attn_kernel<<<16384, 256>>>(q, kv, bt, mask, aob);
    // K5: proj + residual(q_in)  (fp32 out)
    bgemm_kernel<<<dim3(2, 1024), 256>>>(aob, pwb, pb, qin, po, nullptr,
                                         MROWS, 256, 256, 1.f, 2);
    // K6: window reverse + roll + residual with x[:,0]
    reverse_residual_kernel<<<16384, 256>>>(x, po, x1);
    // K7: LN2 (bf16 out)
    ln_rows_kernel<<<16384, 256>>>(x1, g2, b2, x1nb);
    // K8: MLP up + exact gelu (bf16 out)
    bgemm_kernel<<<dim3(8, 1024), 256>>>(x1nb, w1b, bi1, nullptr, nullptr, hb,
                                         MROWS, HID, 256, 1.f, 1);
    // K9: MLP down + residual(x1) -> final output (fp32)
    bgemm_kernel<<<dim3(2, 1024), 256>>>(hb, w2b, bi2, x1, out, nullptr,
                                         MROWS, 256, HID, 1.f, 2);
}